// round 7
// baseline (speedup 1.0000x reference)
#include <cuda_runtime.h>
#include <cstdint>

#define SQ 2048
#define NB 16
#define HD 64
#define MASKW (SQ*SQ/32)        /* 131,072 words = 512 KB */
#define NELEM (NB*SQ*HD)        /* 2,097,152 per tensor */

__device__ uint32_t g_mbits[MASKW];
__device__ float g_q[NELEM];    /* pre-scaled (1/8) + tf32-rounded */
__device__ float g_k[NELEM];    /* tf32-rounded */
__device__ float g_v[NELEM];    /* tf32-rounded */

__device__ __forceinline__ uint32_t cvt_tf32(float x) {
    uint32_t u; asm("cvt.rna.tf32.f32 %0, %1;" : "=r"(u) : "f"(x)); return u;
}
__device__ __forceinline__ uint32_t rotl32(uint32_t x, uint32_t r) {
    return (x << r) | (x >> (32u - r));
}

// threefry2x32 partitionable, key=(0,42): keep decision for counter i
__device__ __forceinline__ bool tf_keep(uint32_t i) {
    const uint32_t ks1 = 42u;
    const uint32_t ks2 = 0x1BD11BDAu ^ 42u;
    uint32_t x0 = 0u, x1 = i + ks1;
#define TFR(r) { x0 += x1; x1 = rotl32(x1, r); x1 ^= x0; }
    TFR(13) TFR(15) TFR(26) TFR(6)
    x0 += ks1; x1 += ks2 + 1u;
    TFR(17) TFR(29) TFR(16) TFR(24)
    x0 += ks2; x1 += 2u;
    TFR(13) TFR(15) TFR(26) TFR(6)
    x1 += ks1 + 3u;
    TFR(17) TFR(29) TFR(16) TFR(24)
    x0 += ks1; x1 += ks2 + 4u;
    TFR(13) TFR(15) TFR(26) TFR(6)
    x0 += ks2; x1 += 5u;
#undef TFR
    return ((x0 ^ x1) >> 9) < 7549747u;
}

// ===========================================================================
// pre-round Q (scaled), K, V to tf32 values stored as fp32
// ===========================================================================
__global__ void round_kernel(const float4* __restrict__ q,
                             const float4* __restrict__ k,
                             const float4* __restrict__ v) {
    int i = blockIdx.x * blockDim.x + threadIdx.x;
    float4 t = __ldg(q + i);
    float4 u;
    u.x = __uint_as_float(cvt_tf32(t.x * 0.125f));
    u.y = __uint_as_float(cvt_tf32(t.y * 0.125f));
    u.z = __uint_as_float(cvt_tf32(t.z * 0.125f));
    u.w = __uint_as_float(cvt_tf32(t.w * 0.125f));
    ((float4*)g_q)[i] = u;
    t = __ldg(k + i);
    u.x = __uint_as_float(cvt_tf32(t.x));
    u.y = __uint_as_float(cvt_tf32(t.y));
    u.z = __uint_as_float(cvt_tf32(t.z));
    u.w = __uint_as_float(cvt_tf32(t.w));
    ((float4*)g_k)[i] = u;
    t = __ldg(v + i);
    u.x = __uint_as_float(cvt_tf32(t.x));
    u.y = __uint_as_float(cvt_tf32(t.y));
    u.z = __uint_as_float(cvt_tf32(t.z));
    u.w = __uint_as_float(cvt_tf32(t.w));
    ((float4*)g_v)[i] = u;
}

// ===========================================================================
// pack attn_mask into bits (bit=1 -> unmasked)
// ===========================================================================
__global__ void pack_mask_kernel(const int* __restrict__ mask) {
    uint32_t lane = threadIdx.x & 31u;
    uint32_t warp = (blockIdx.x * blockDim.x + threadIdx.x) >> 5;
    uint32_t nw   = (gridDim.x * blockDim.x) >> 5;
    for (uint32_t w = warp * 4u; w < MASKW; w += nw * 4u) {
        int v0 = __ldg(mask + (size_t)w * 32 + lane);
        int v1 = __ldg(mask + (size_t)(w + 1) * 32 + lane);
        int v2 = __ldg(mask + (size_t)(w + 2) * 32 + lane);
        int v3 = __ldg(mask + (size_t)(w + 3) * 32 + lane);
        uint4 b;
        b.x = __ballot_sync(0xffffffffu, v0 != 0);
        b.y = __ballot_sync(0xffffffffu, v1 != 0);
        b.z = __ballot_sync(0xffffffffu, v2 != 0);
        b.w = __ballot_sync(0xffffffffu, v3 != 0);
        if (lane == 0) *(uint4*)(g_mbits + w) = b;
    }
}

// ===========================================================================
// fused tf32 mma.sync flash attention + inline threefry dropout
// CTA: 64 q-rows, 4 warps x 16 rows. 512 CTAs (3/SM). Key tile 64,
// cp.async double-buffered. P refragmented via intra-quad shuffles (no smem).
// K pitch 68 (conflict-free frag reads), V pitch 72 (conflict-free).
// ===========================================================================

#define KPITCH 68
#define VPITCH 72
#define KBUF (64*KPITCH)                 /* 4352 floats */
#define VBUF (64*VPITCH)                 /* 4608 floats */
#define BUFSZ (KBUF+VBUF)                /* 8960 floats per stage buffer */
#define SMEM_BYTES (2*BUFSZ*4)           /* 71,680 B -> 3 CTAs/SM */

#define CP16(dst, src) asm volatile("cp.async.cg.shared.global [%0], [%1], 16;" :: "r"(dst), "l"(src) : "memory")
#define CP_COMMIT()    asm volatile("cp.async.commit_group;" ::: "memory")
#define CP_WAIT0()     asm volatile("cp.async.wait_group 0;" ::: "memory")

__device__ __forceinline__ uint32_t s2u(const void* p) {
    uint32_t a;
    asm("{ .reg .u64 t; cvta.to.shared.u64 t, %1; cvt.u32.u64 %0, t; }" : "=r"(a) : "l"(p));
    return a;
}

__device__ __forceinline__ void mma_tf32(float c[4], const uint32_t a[4],
                                         uint32_t b0, uint32_t b1) {
    asm volatile(
        "mma.sync.aligned.m16n8k8.row.col.f32.tf32.tf32.f32 "
        "{%0,%1,%2,%3}, {%4,%5,%6,%7}, {%8,%9}, {%0,%1,%2,%3};"
        : "+f"(c[0]), "+f"(c[1]), "+f"(c[2]), "+f"(c[3])
        : "r"(a[0]), "r"(a[1]), "r"(a[2]), "r"(a[3]), "r"(b0), "r"(b1));
}

__global__ void __launch_bounds__(128, 3) flash_mma_kernel(float* __restrict__ out)
{
    extern __shared__ float sm[];
    const uint32_t sb = s2u(sm);

    const int tid  = threadIdx.x;
    const int wid  = tid >> 5;
    const int lane = tid & 31;
    const int g    = lane >> 2;
    const int e    = lane & 3;
    const int b    = blockIdx.x >> 5;
    const int qt   = blockIdx.x & 31;
    const int qbw  = qt * 64 + wid * 16;          // warp's q-row base
    const float INVK = (float)(1.0 / 0.9);

    // staging role: 2 threads per row, 64 rows
    const int srow = tid >> 1;
    const int shf  = tid & 1;
    const float* ksrc = g_k + ((size_t)(b * SQ + srow)) * HD + shf * 32;
    const float* vsrc = g_v + ((size_t)(b * SQ + srow)) * HD + shf * 32;
    const uint32_t kdst = sb + (uint32_t)((srow * KPITCH + shf * 32) * 4);
    const uint32_t vdst = sb + (uint32_t)((KBUF + srow * VPITCH + shf * 32) * 4);

    // ---- Q fragments (16 rows/warp), persistent ----
    uint32_t qa[8][4];
    {
        const float* q0 = g_q + ((size_t)(b * SQ + qbw + g)) * HD + e;
        const float* q1 = q0 + 8 * HD;
#pragma unroll
        for (int kf = 0; kf < 8; kf++) {
            qa[kf][0] = __float_as_uint(__ldg(q0 + kf * 8));
            qa[kf][1] = __float_as_uint(__ldg(q1 + kf * 8));
            qa[kf][2] = __float_as_uint(__ldg(q0 + kf * 8 + 4));
            qa[kf][3] = __float_as_uint(__ldg(q1 + kf * 8 + 4));
        }
    }

    float dpv[8][4];
#pragma unroll
    for (int nf = 0; nf < 8; nf++)
#pragma unroll
        for (int j = 0; j < 4; j++) dpv[nf][j] = 0.0f;
    float l0 = 0.0f, l1 = 0.0f;

    // threefry counter bases for my two rows (col term 2e folded in)
    const uint32_t ctr0 = ((uint32_t)(b * SQ + qbw + g) << 11) + 2u * (uint32_t)e;
    const uint32_t ctr1 = ctr0 + (8u << 11);
    const uint32_t* mb0 = g_mbits + (size_t)(qbw + g) * (SQ / 32);
    const uint32_t* mb1 = mb0 + 8 * (SQ / 32);

    const int src  = (lane & ~3) | (e >> 1);      // shfl source lanes (in-quad)
    const int src2 = src + 2;
    const bool eodd = (e & 1);

    // ---- prologue: stage tile 0 into buffer 0 ----
#pragma unroll
    for (int c = 0; c < 8; c++) {
        CP16(kdst + c * 16, ksrc + c * 4);
        CP16(vdst + c * 16, vsrc + c * 4);
    }
    CP_COMMIT(); CP_WAIT0();
    __syncthreads();

    for (int it = 0; it < 32; it++) {
        const int cur = it & 1;
        float* Ks = sm + cur * BUFSZ;
        float* Vs = Ks + KBUF;

        // ---- stage next tile ----
        if (it < 31) {
            const uint32_t boff = (uint32_t)((cur ^ 1) * BUFSZ * 4);
            const float* kn = ksrc + (size_t)(it + 1) * 64 * HD;
            const float* vn = vsrc + (size_t)(it + 1) * 64 * HD;
#pragma unroll
            for (int c = 0; c < 8; c++) {
                CP16(kdst + boff + c * 16, kn + c * 4);
                CP16(vdst + boff + c * 16, vn + c * 4);
            }
            CP_COMMIT();
        }

        const uint2 mw0 = *(const uint2*)(mb0 + it * 2);
        const uint2 mw1 = *(const uint2*)(mb1 + it * 2);
        const uint32_t cbase = (uint32_t)(it * 64);

#pragma unroll
        for (int nf = 0; nf < 8; nf++) {
            // ---- S block [16 x 8] = Q . K^T ----
            float c[4] = {0.f, 0.f, 0.f, 0.f};
#pragma unroll
            for (int kf = 0; kf < 8; kf++) {
                const float* kr = Ks + (nf * 8 + g) * KPITCH + kf * 8 + e;
                mma_tf32(c, qa[kf], __float_as_uint(kr[0]), __float_as_uint(kr[4]));
            }

            // ---- inline threefry keep bits (2 rows x 2 cols) ----
            const uint32_t cc = cbase + (uint32_t)(nf * 8);
            const bool k00 = tf_keep(ctr0 + cc);
            const bool k01 = tf_keep(ctr0 + cc + 1);
            const bool k10 = tf_keep(ctr1 + cc);
            const bool k11 = tf_keep(ctr1 + cc + 1);

            // ---- epilogue: mask -> exp -> l -> dropout -> tf32 ----
            const uint32_t m0 = (nf < 4) ? mw0.x : mw0.y;
            const uint32_t m1 = (nf < 4) ? mw1.x : mw1.y;
            const int bit = (nf & 3) * 8 + 2 * e;
            float p0 = ((m0 >> bit) & 1u)       ? __expf(c[0]) : 0.0f;
            float p1 = ((m0 >> (bit + 1)) & 1u) ? __expf(c[1]) : 0.0f;
            float p2 = ((m1 >> bit) & 1u)       ? __expf(c[2]) : 0.0f;
            float p3 = ((m1 >> (bit + 1)) & 1u) ? __expf(c[3]) : 0.0f;
            l0 += p0 + p1;
            l1 += p2 + p3;
            uint32_t u0 = cvt_tf32(k00 ? p0 * INVK : 0.0f);
            uint32_t u1 = cvt_tf32(k01 ? p1 * INVK : 0.0f);
            uint32_t u2 = cvt_tf32(k10 ? p2 * INVK : 0.0f);
            uint32_t u3 = cvt_tf32(k11 ? p3 * INVK : 0.0f);

            // ---- refragment D(m16n8) -> A(m16n8k8) via intra-quad shuffles ----
            uint32_t a[4];
            {
                uint32_t t0 = __shfl_sync(0xffffffffu, u0, src);
                uint32_t t1 = __shfl_sync(0xffffffffu, u1, src);
                a[0] = eodd ? t1 : t0;
                uint32_t t2 = __shfl_sync(0xffffffffu, u2, src);
                uint32_t t3 = __shfl_sync(0xffffffffu, u3, src);
                a[1] = eodd ? t3 : t2;
                uint32_t t4 = __shfl_sync(0xffffffffu, u0, src2);
                uint32_t t5 = __shfl_sync(0xffffffffu, u1, src2);
                a[2] = eodd ? t5 : t4;
                uint32_t t6 = __shfl_sync(0xffffffffu, u2, src2);
                uint32_t t7 = __shfl_sync(0xffffffffu, u3, src2);
                a[3] = eodd ? t7 : t6;
            }

            // ---- D_pv += P_block . V[kb=nf] ----
#pragma unroll
            for (int nf2 = 0; nf2 < 8; nf2++) {
                const float* vr = Vs + (nf * 8 + e) * VPITCH + nf2 * 8 + g;
                mma_tf32(dpv[nf2], a, __float_as_uint(vr[0]),
                         __float_as_uint(vr[4 * VPITCH]));
            }
        }

        if (it < 31) CP_WAIT0();
        __syncthreads();
    }

    // ---- reduce l across quad, normalize, store ----
    l0 += __shfl_xor_sync(0xffffffffu, l0, 1);
    l0 += __shfl_xor_sync(0xffffffffu, l0, 2);
    l1 += __shfl_xor_sync(0xffffffffu, l1, 1);
    l1 += __shfl_xor_sync(0xffffffffu, l1, 2);
    const float inv0 = 1.0f / l0;
    const float inv1 = 1.0f / l1;

    float* op0 = out + ((size_t)(b * SQ + qbw + g)) * HD + 2 * e;
    float* op1 = op0 + 8 * HD;
#pragma unroll
    for (int nf2 = 0; nf2 < 8; nf2++) {
        float2 t;
        t.x = dpv[nf2][0] * inv0;
        t.y = dpv[nf2][1] * inv0;
        *(float2*)(op0 + nf2 * 8) = t;
        t.x = dpv[nf2][2] * inv1;
        t.y = dpv[nf2][3] * inv1;
        *(float2*)(op1 + nf2 * 8) = t;
    }
}

// ===========================================================================
extern "C" void kernel_launch(void* const* d_in, const int* in_sizes, int n_in,
                              void* d_out, int out_size) {
    const float4* q = (const float4*)d_in[0];
    const float4* k = (const float4*)d_in[1];
    const float4* v = (const float4*)d_in[2];
    const int* mask = (const int*)d_in[3];
    float* out = (float*)d_out;

    cudaFuncSetAttribute(flash_mma_kernel,
                         cudaFuncAttributeMaxDynamicSharedMemorySize, SMEM_BYTES);

    round_kernel<<<NELEM / 4 / 256, 256>>>(q, k, v);
    pack_mask_kernel<<<1024, 256>>>(mask);
    flash_mma_kernel<<<NB * (SQ / 64), 128, SMEM_BYTES>>>(out);
}